// round 17
// baseline (speedup 1.0000x reference)
#include <cuda_runtime.h>
#include <cuda_bf16.h>

#define VOCAB    128000
#define HISTLEN  2048
#define TOPK     15
#define KC       20            // carried keys (> TOPK to absorb pivot ties)
#define NBLK     125           // 125 * 1024 == 128000 exactly
#define NTHR     1024
#define NWARP    (NTHR / 32)   // 32
#define NEG_KEY  0ull

// -------- device scratch (allocations forbidden; self-cleaning) --------
__device__ unsigned long long g_btop[NBLK * KC];   // fully rewritten each call
__device__ unsigned           g_cnt1;              // reset by last block

// monotone map float -> unsigned (total order; NaN above +inf) + inverse
__device__ __forceinline__ unsigned ordered(float f) {
    unsigned u = __float_as_uint(f);
    return u ^ ((u & 0x80000000u) ? 0xFFFFFFFFu : 0x80000000u);
}
__device__ __forceinline__ float unordered(unsigned x) {
    unsigned u = (x & 0x80000000u) ? (x ^ 0x80000000u) : (x ^ 0xFFFFFFFFu);
    return __uint_as_float(u);
}
__device__ __forceinline__ unsigned long long warp_max(unsigned long long k) {
    #pragma unroll
    for (int off = 16; off; off >>= 1) {
        unsigned long long o = __shfl_xor_sync(0xffffffffu, k, off);
        if (o > k) k = o;
    }
    return k;
}
// extract current max of shared slice [lo,hi) (warp-collective), pop it
__device__ __forceinline__ unsigned long long
slice_extract(volatile unsigned long long* arr, int lo, int hi, int lane) {
    unsigned long long lm = NEG_KEY; int lp = lo;
    for (int j = lo + lane; j < hi; j += 32) {
        unsigned long long x = arr[j];
        if (x > lm) { lm = x; lp = j; }
    }
    unsigned long long m = warp_max(lm);
    if (lm == m && lm != NEG_KEY) arr[lp] = NEG_KEY;   // unique keys: one owner
    __syncwarp();
    return m;
}

__global__ void __launch_bounds__(NTHR, 1)
k_all(const float* __restrict__ logits, const int* __restrict__ y,
      const float* __restrict__ noise, float* __restrict__ out, int out_size) {
    __shared__ unsigned           sbm[32];             // range bitmap (1024 ids)
    __shared__ unsigned long long swtop[NWARP * KC];   // 640 keys
    __shared__ unsigned long long s2[8 * KC];          // 160 keys
    __shared__ unsigned long long sall[NBLK * KC];     // 2500 keys (last block)
    __shared__ unsigned long long fin[KC];
    __shared__ int                sidx[KC];
    __shared__ int s_flag;

    const int tid = threadIdx.x, lane = tid & 31, w = tid >> 5;
    const int i = blockIdx.x * NTHR + tid;             // exactly covers VOCAB

    float lv = logits[i];                              // early load

    // ---- block-range membership bitmap (32 words; barrier-free design) -----
    if (tid < 32) sbm[tid] = 0u;
    __syncthreads();
    {
        int t0 = tid, t1 = tid + NTHR;                 // HISTLEN == 2 * NTHR
        int p0 = y[t0], p1 = y[t1];
        if (blockIdx.x == 0 && out_size >= HISTLEN + 2) {
            out[1 + t0] = (float)p0;                   // y_new copy, exact <2^24
            out[1 + t1] = (float)p1;
        }
        p0 = min(max(p0, 0), VOCAB - 1);               // clamp: OOB impossible
        p1 = min(max(p1, 0), VOCAB - 1);
        if ((p0 >> 10) == (int)blockIdx.x)
            atomicOr(&sbm[(p0 & 1023) >> 5], 1u << (p0 & 31));
        if ((p1 >> 10) == (int)blockIdx.x)
            atomicOr(&sbm[(p1 & 1023) >> 5], 1u << (p1 & 31));
    }
    __syncthreads();

    // ---- penalty (regs). _rn ops bit-match the f32 reference; value depends
    // only on the ORIGINAL logit so duplicate history tokens are harmless.
    if ((sbm[(i & 1023) >> 5] >> (i & 31)) & 1u)
        lv = (lv < 0.0f) ? __fmul_rn(lv, 1.35f) : __fdiv_rn(lv, 1.35f);

    // ---- warp bitonic full sort (ascending) of 32 unique keys ---------------
    unsigned long long key = ((unsigned long long)ordered(lv) << 32)
                           | (unsigned long long)(0xFFFFFFFFu - (unsigned)i);
    #pragma unroll
    for (int k = 2; k <= 32; k <<= 1) {
        #pragma unroll
        for (int j = k >> 1; j > 0; j >>= 1) {
            unsigned long long o = __shfl_xor_sync(0xffffffffu, key, j);
            bool up = ((lane & k) == 0);
            bool hi = ((lane & j) != 0);
            unsigned long long mn = (key < o) ? key : o;
            unsigned long long mx = (key < o) ? o : key;
            key = (hi == up) ? mx : mn;
        }
    }
    if (lane >= 32 - KC) swtop[w * KC + (31 - lane)] = key;   // warp top-20
    __syncthreads();

    // ---- block merge: 640 -> 160 (8 warps x 80) -> 20 (warp 0) --------------
    if (w < 8) {
        int lo = w * (NWARP * KC / 8), hi2 = lo + (NWARP * KC / 8);
        for (int k = 0; k < KC; k++) {
            unsigned long long m = slice_extract(swtop, lo, hi2, lane);
            if (lane == 0) s2[w * KC + k] = m;
        }
    }
    __syncthreads();
    if (w == 0) {
        for (int k = 0; k < KC; k++) {
            unsigned long long m = slice_extract(s2, 0, 8 * KC, lane);
            if (lane == 0) g_btop[blockIdx.x * KC + k] = m;
        }
    }
    __syncthreads();

    // ---- exit counter: LAST block does the entire finale ---------------------
    if (tid == 0) {
        __threadfence();                               // publish g_btop
        s_flag = (atomicAdd(&g_cnt1, 1u) == NBLK - 1);
        if (s_flag) g_cnt1 = 0u;                       // self-clean
    }
    __syncthreads();
    if (!s_flag) return;
    __threadfence();                                   // acquire all g_btop
    for (int j = tid; j < NBLK * KC; j += NTHR) sall[j] = g_btop[j];
    __syncthreads();
    {   // level 1: 32 warps x 79 keys -> 640
        int lo = w * 79, hi2 = min(lo + 79, NBLK * KC);
        for (int k = 0; k < KC; k++) {
            unsigned long long m = slice_extract(sall, lo, hi2, lane);
            if (lane == 0) swtop[w * KC + k] = m;
        }
    }
    __syncthreads();
    if (w < 8) {        // level 2: 8 warps x 80 -> 160
        int lo = w * (NWARP * KC / 8), hi2 = lo + (NWARP * KC / 8);
        for (int k = 0; k < KC; k++) {
            unsigned long long m = slice_extract(swtop, lo, hi2, lane);
            if (lane == 0) s2[w * KC + k] = m;
        }
    }
    __syncthreads();
    if (w == 0) {       // level 3: 160 -> global top-20 keys (descending)
        for (int k = 0; k < KC; k++) {
            unsigned long long m = slice_extract(s2, 0, 8 * KC, lane);
            if (lane == 0) {
                fin[k]  = m;
                sidx[k] = (int)(0xFFFFFFFFu - (unsigned)(m & 0xFFFFFFFFull));
            }
        }
        __syncwarp();

        // ---- finale on one warp: reference numerics on the kept set ---------
        // kept = all elements with value >= 15th value (handles pivot ties).
        // Masked elements are all exactly +-0 in probs/noise (unified class,
        // earliest index m0 wins among them). Kept: (exp(l-lmax)/S)/nz with
        // __fdiv_rn — bit-identical to rounds 9-16's validated formula.
        float lmax = unordered((unsigned)(fin[0] >> 32));
        float pivv = unordered((unsigned)(fin[TOPK - 1] >> 32));
        int   myidx = 0; float mylv = 0.0f;
        if (lane < KC) {
            myidx = sidx[lane];
            mylv  = unordered((unsigned)(fin[lane] >> 32));
        }
        bool kept = (lane < KC) && (mylv >= pivv);
        unsigned nkball = __ballot_sync(0xffffffffu, kept);
        int nk = __popc(nkball);                       // kept prefix length
        float nz = (lane < KC) ? noise[myidx] : 1.0f;  // 20-element gather
        float S = 0.0f;
        if (lane == 0) {                               // sequential, descending
            for (int k = 0; k < nk; k++)
                S += expf(unordered((unsigned)(fin[k] >> 32)) - lmax);
        }
        S = __shfl_sync(0xffffffffu, S, 0);
        unsigned long long myk = NEG_KEY;
        if (kept) {
            float v = __fdiv_rn(__fdiv_rn(expf(mylv - lmax), S), nz);
            unsigned ov = (v == 0.0f) ? 0x80000000u : ordered(v);
            myk = ((unsigned long long)ov << 32)
                | (unsigned long long)(0xFFFFFFFFu - (unsigned)myidx);
        }
        // first masked index m0 (smallest integer not among kept indices)
        bool masked = true;
        for (int t = 0; t < nk; t++) if (sidx[t] == lane) masked = false;
        unsigned mball = __ballot_sync(0xffffffffu, masked);  // lanes 0..31
        int m0 = __ffs(mball) - 1;                     // nk<=20 -> exists
        if (lane == 31)                                // zero-class contender
            myk = (0x80000000ull << 32)
                | (unsigned long long)(0xFFFFFFFFu - (unsigned)m0);
        unsigned long long win = warp_max(myk);
        if (lane == 0) {
            float fidx = (float)(int)(0xFFFFFFFFu - (unsigned)(win & 0xFFFFFFFFull));
            out[0] = fidx;                                         // samples
            if (out_size >= HISTLEN + 2) out[1 + HISTLEN] = fidx;  // y_new tail
            for (int j = HISTLEN + 2; j < out_size; j++) out[j] = fidx;
        }
    }
}

extern "C" void kernel_launch(void* const* d_in, const int* in_sizes, int n_in,
                              void* d_out, int out_size) {
    // y = the size-2048 tensor; among the remaining two (metadata order),
    // logits precedes noise (validated rounds 9-16).
    int iy = 1;
    for (int i = 0; i < n_in; i++) if (in_sizes[i] == HISTLEN) { iy = i; break; }
    int fl[2]; int nf = 0;
    for (int i = 0; i < n_in && nf < 2; i++) if (i != iy) fl[nf++] = i;

    const float* logits = (const float*)d_in[fl[0]];
    const float* noise  = (const float*)d_in[fl[1]];
    const int*   y      = (const int*)d_in[iy];

    k_all<<<NBLK, NTHR>>>(logits, y, noise, (float*)d_out, out_size);
}